// round 8
// baseline (speedup 1.0000x reference)
#include <cuda_runtime.h>
#include <math.h>

#define N_NODES 50000
#define TPB_N   128
#define TPB_E   256
#define GRID_E  592          // 148 SMs * 4 CTAs -> exactly one wave

// Scratch (allocation-free __device__ globals). Zero-initialized at load;
// K2's last block resets counters each launch -> deterministic across replays.
__device__ double   g_acc;
__device__ unsigned g_done;
__device__ float4   g_vtab[8 * N_NODES];    // [rel][node]: (v0, v1, vb, 0)

__device__ __forceinline__ double block_reduce(double v, int nthreads) {
    __shared__ double sh[8];
    int lane = threadIdx.x & 31, wid = threadIdx.x >> 5;
    #pragma unroll
    for (int off = 16; off; off >>= 1) v += __shfl_down_sync(0xffffffffu, v, off);
    if (lane == 0) sh[wid] = v;
    __syncthreads();
    int nw = nthreads >> 5;
    v = (threadIdx.x < nw) ? sh[threadIdx.x] : 0.0;
    if (wid == 0) {
        #pragma unroll
        for (int off = 4; off; off >>= 1) v += __shfl_down_sync(0xffffffffu, v, off);
    }
    return v;
}

// ---------------------------------------------------------------------------
// K1: node pass with per-block inline setup (no separate setup kernel).
// Setup (per block, in SMEM): 16 length-64 weight rows
//   rows c*4+b (c<3,b<4): t[c][b][o] = sum_i hv[c][i]*bases[b,i,o]
//   rows 12..14:          sl[c][o]   = sum_i hv[c][i]*loop_w[i,o]
//   row  15:              h_bias
//   hv[0]=W_in[0,:], hv[1]=W_in[1,:], hv[2]=b_in
// Node pass: fcW tile staged through SMEM (coalesced, padded rows); 16
// accumulators/node; vtab stored [rel][node] (coalesced warp stores).
// Self-loop readout: f.x*p12 + f.y*p13 + p14 + p15 -> g_acc.
// ---------------------------------------------------------------------------
#define TSTRIDE 68           // floats per padded tile row (16B-aligned rows)

__global__ void __launch_bounds__(TPB_N)
k_node(const float2* __restrict__ feats,
       const float* __restrict__ W_in, const float* __restrict__ b_in,
       const float* __restrict__ w_comp, const float* __restrict__ bases,
       const float* __restrict__ loop_w, const float* __restrict__ h_bias,
       const float* __restrict__ fcW)
{
    __shared__ float  tile[TPB_N * TSTRIDE];   // 34 KB
    __shared__ float  hv[3 * 64];
    __shared__ float4 ws[16 * 16];             // 16 rows x 64 floats as float4
    __shared__ float  wc[32];
    float* wsf = (float*)ws;
    int tid = threadIdx.x;

    // hv fill + w_comp copy
    for (int i = tid; i < 192; i += TPB_N) {
        int c = i >> 6, o = i & 63;
        hv[i] = (c < 2) ? W_in[c * 64 + o] : b_in[o];
    }
    if (tid < 32) wc[tid] = w_comp[tid];
    __syncthreads();

    // Inline setup: 1024 outputs over 128 threads (coalesced loads from M).
    for (int u = tid; u < 1024; u += TPB_N) {
        int row = u >> 6, o = u & 63;
        float s;
        if (row == 15) {
            s = h_bias[o];
        } else {
            int c; const float* M;
            if (row < 12) { c = row >> 2; M = bases + (row & 3) * 4096; }
            else          { c = row - 12; M = loop_w; }
            s = 0.f;
            #pragma unroll 16
            for (int i = 0; i < 64; i++)
                s += hv[c * 64 + i] * __ldg(&M[i * 64 + o]);
        }
        wsf[u] = s;
    }

    // Stage this block's fcW tile into SMEM (coalesced 128B warp loads).
    int nbase = blockIdx.x * TPB_N;
    int nblk  = min(TPB_N, N_NODES - nbase);
    const float4* src4 = (const float4*)(fcW + (size_t)nbase * 64);
    int total4 = nblk * 16;
    for (int idx = tid; idx < total4; idx += TPB_N) {
        float4 f = src4[idx];
        int node = idx >> 4, j4 = idx & 15;
        ((float4*)(tile + node * TSTRIDE))[j4] = f;
    }
    __syncthreads();

    double contrib = 0.0;
    if (tid < nblk) {
        int n = nbase + tid;
        const float4* F4 = (const float4*)(tile + tid * TSTRIDE);
        float acc[16];
        #pragma unroll
        for (int k = 0; k < 16; k++) acc[k] = 0.f;
        #pragma unroll 4
        for (int j = 0; j < 16; j++) {
            float4 f = F4[j];
            #pragma unroll
            for (int k = 0; k < 16; k++) {
                float4 w = ws[k * 16 + j];
                acc[k] += f.x * w.x + f.y * w.y + f.z * w.z + f.w * w.w;
            }
        }
        #pragma unroll
        for (int r = 0; r < 8; r++) {
            float4 v;
            v.x = wc[r*4]*acc[0] + wc[r*4+1]*acc[1] + wc[r*4+2]*acc[2]  + wc[r*4+3]*acc[3];
            v.y = wc[r*4]*acc[4] + wc[r*4+1]*acc[5] + wc[r*4+2]*acc[6]  + wc[r*4+3]*acc[7];
            v.z = wc[r*4]*acc[8] + wc[r*4+1]*acc[9] + wc[r*4+2]*acc[10] + wc[r*4+3]*acc[11];
            v.w = 0.f;
            g_vtab[r * N_NODES + n] = v;     // lane-coalesced per r
        }
        float2 f = feats[n];
        contrib = (double)(f.x * acc[12] + f.y * acc[13] + acc[14] + acc[15]);
    }
    double bs = block_reduce(contrib, TPB_N);
    if (tid == 0) atomicAdd(&g_acc, bs);
}

// ---------------------------------------------------------------------------
// K2: edge pass + finalize. Default cache policy; exactly one wave
// (592 blocks @ 4 CTAs/SM); 4 edges per iteration via int4 indices.
// vtab indexed [rel][node].
// ---------------------------------------------------------------------------
__global__ void __launch_bounds__(TPB_E, 4)
k_edge(const float2* __restrict__ feats,
       const int* __restrict__ src, const int* __restrict__ dst,
       const int* __restrict__ et, const float* __restrict__ fc_b,
       int E, float* __restrict__ out)
{
    double contrib = 0.0;
    int nvec = E >> 2;
    const int4* s4p = (const int4*)src;
    const int4* d4p = (const int4*)dst;
    const int4* r4p = (const int4*)et;
    for (int i = blockIdx.x * TPB_E + threadIdx.x; i < nvec; i += GRID_E * TPB_E) {
        int4 s4 = s4p[i], d4 = d4p[i], r4 = r4p[i];
        float2 fa = feats[s4.x], fb = feats[s4.y], fc = feats[s4.z], fd = feats[s4.w];
        float4 va = g_vtab[r4.x * N_NODES + d4.x];
        float4 vb = g_vtab[r4.y * N_NODES + d4.y];
        float4 vc = g_vtab[r4.z * N_NODES + d4.z];
        float4 vd = g_vtab[r4.w * N_NODES + d4.w];
        float esum = fmaf(fa.x, va.x, fmaf(fa.y, va.y, va.z))
                   + fmaf(fb.x, vb.x, fmaf(fb.y, vb.y, vb.z))
                   + fmaf(fc.x, vc.x, fmaf(fc.y, vc.y, vc.z))
                   + fmaf(fd.x, vd.x, fmaf(fd.y, vd.y, vd.z));
        contrib += (double)esum;
    }
    for (int e = (nvec << 2) + blockIdx.x * TPB_E + threadIdx.x; e < E; e += GRID_E * TPB_E) {
        float2 f = feats[src[e]];
        float4 v = g_vtab[et[e] * N_NODES + dst[e]];
        contrib += (double)fmaf(f.x, v.x, fmaf(f.y, v.y, v.z));
    }

    double bs = block_reduce(contrib, TPB_E);
    if (threadIdx.x == 0) {
        atomicAdd(&g_acc, bs);
        __threadfence();
        unsigned d = atomicAdd(&g_done, 1u);
        if (d == GRID_E - 1) {
            double logit = atomicAdd(&g_acc, 0.0) + (double)fc_b[0];
            out[0] = (float)(1.0 / (1.0 + exp(-logit)));
            g_acc = 0.0;       // reset for next graph replay
            g_done = 0u;
        }
    }
}

extern "C" void kernel_launch(void* const* d_in, const int* in_sizes, int n_in,
                              void* d_out, int out_size) {
    const float* features = (const float*)d_in[0];
    const int*   src      = (const int*)d_in[1];
    const int*   dst      = (const int*)d_in[2];
    const int*   etype    = (const int*)d_in[3];
    const float* W_in     = (const float*)d_in[4];
    const float* b_in     = (const float*)d_in[5];
    const float* w_comp   = (const float*)d_in[6];
    const float* bases    = (const float*)d_in[7];
    const float* loop_w   = (const float*)d_in[8];
    const float* h_bias   = (const float*)d_in[9];
    const float* fc_W     = (const float*)d_in[10];
    const float* fc_b     = (const float*)d_in[11];
    int E = in_sizes[1];

    k_node<<<(N_NODES + TPB_N - 1) / TPB_N, TPB_N>>>((const float2*)features,
                                                     W_in, b_in, w_comp, bases,
                                                     loop_w, h_bias, fc_W);
    k_edge<<<GRID_E, TPB_E>>>((const float2*)features, src, dst, etype,
                              fc_b, E, (float*)d_out);
}

// round 9
// speedup vs baseline: 1.1989x; 1.1989x over previous
#include <cuda_runtime.h>
#include <math.h>

#define N_NODES 50000
#define TPB_N   128
#define TPB_E   128
#define GRID_E  1184         // 148 SMs * 8 CTAs -> exactly one wave

// Scratch (allocation-free __device__ globals). Zero-initialized at load;
// K2's last block resets counters each launch -> deterministic across replays.
__device__ double   g_acc;
__device__ unsigned g_done;
__device__ unsigned g_ready;                // setup rows published (0..16)
__device__ float    g_Wt[16 * 64];          // 16 weight rows
__device__ float4   g_vtab[8 * N_NODES];    // [rel][node]: (v0, v1, vb, 0)

__device__ __forceinline__ double block_reduce(double v, int nthreads) {
    __shared__ double sh[8];
    int lane = threadIdx.x & 31, wid = threadIdx.x >> 5;
    #pragma unroll
    for (int off = 16; off; off >>= 1) v += __shfl_down_sync(0xffffffffu, v, off);
    if (lane == 0) sh[wid] = v;
    __syncthreads();
    int nw = nthreads >> 5;
    v = (threadIdx.x < nw) ? sh[threadIdx.x] : 0.0;
    if (wid == 0) {
        #pragma unroll
        for (int off = 4; off; off >>= 1) v += __shfl_down_sync(0xffffffffu, v, off);
    }
    return v;
}

// ---------------------------------------------------------------------------
// K1: node pass; blocks 0..15 also each compute ONE row of the 16x64 weight
// table (no redundancy), publish via g_ready. All 391 blocks are co-resident
// (smem ~40KB -> >=4 CTAs/SM capacity), so the spin cannot deadlock.
// Weight rows:
//   rows c*4+b (c<3,b<4): t[c][b][o] = sum_i hv[c][i]*bases[b,i,o]
//   rows 12..14:          sl[c][o]   = sum_i hv[c][i]*loop_w[i,o]
//   row  15:              h_bias
//   hv[0]=W_in[0,:], hv[1]=W_in[1,:], hv[2]=b_in
// Node pass: fcW tile staged via SMEM (coalesced, padded rows); 16
// accumulators/node; vtab stored [rel][node] (coalesced warp stores).
// ---------------------------------------------------------------------------
#define TSTRIDE 68           // floats per padded tile row (16B-aligned rows)

__global__ void __launch_bounds__(TPB_N)
k_node(const float2* __restrict__ feats,
       const float* __restrict__ W_in, const float* __restrict__ b_in,
       const float* __restrict__ w_comp, const float* __restrict__ bases,
       const float* __restrict__ loop_w, const float* __restrict__ h_bias,
       const float* __restrict__ fcW)
{
    __shared__ float  tile[TPB_N * TSTRIDE];   // 34 KB
    __shared__ float4 ws[16 * 16];
    __shared__ float  wc[32];
    __shared__ float  hv[64];
    __shared__ float  part[2][64];
    int tid = threadIdx.x;

    if (tid < 32) wc[tid] = w_comp[tid];

    // --- Setup duty for blocks 0..15: compute g_Wt row blockIdx.x ---
    if (blockIdx.x < 16) {
        int row = blockIdx.x;
        if (row == 15) {
            if (tid < 64) g_Wt[15 * 64 + tid] = h_bias[tid];
        } else {
            int c; const float* M;
            if (row < 12) { c = row >> 2; M = bases + (row & 3) * 4096; }
            else          { c = row - 12; M = loop_w; }
            if (tid < 64) hv[tid] = (c < 2) ? W_in[c * 64 + tid] : b_in[tid];
            __syncthreads();
            int o = tid & 63, q = tid >> 6;       // 2-way i-split of 32 each
            float s = 0.f;
            int i0 = q * 32;
            #pragma unroll 16
            for (int i = 0; i < 32; i++)
                s += hv[i0 + i] * __ldg(&M[(i0 + i) * 64 + o]);
            part[q][o] = s;
            __syncthreads();
            if (tid < 64)
                g_Wt[row * 64 + tid] = part[0][tid] + part[1][tid];
        }
        __syncthreads();
        if (tid == 0) {
            __threadfence();
            atomicAdd(&g_ready, 1u);
        }
    }

    // --- Stage this block's fcW tile into SMEM (coalesced warp loads) ---
    int nbase = blockIdx.x * TPB_N;
    int nblk  = min(TPB_N, N_NODES - nbase);
    const float4* src4 = (const float4*)(fcW + (size_t)nbase * 64);
    int total4 = nblk * 16;
    for (int idx = tid; idx < total4; idx += TPB_N) {
        float4 f = src4[idx];
        int node = idx >> 4, j4 = idx & 15;
        ((float4*)(tile + node * TSTRIDE))[j4] = f;
    }

    // --- Wait for all 16 weight rows, then pull them into SMEM ---
    if (tid == 0) {
        while (atomicAdd(&g_ready, 0u) < 16u) { }
        __threadfence();
    }
    __syncthreads();
    for (int i = tid; i < 16 * 16; i += TPB_N)
        ws[i] = ((const float4*)g_Wt)[i];
    __syncthreads();

    // --- Per-node math ---
    double contrib = 0.0;
    if (tid < nblk) {
        int n = nbase + tid;
        const float4* F4 = (const float4*)(tile + tid * TSTRIDE);
        float acc[16];
        #pragma unroll
        for (int k = 0; k < 16; k++) acc[k] = 0.f;
        #pragma unroll 4
        for (int j = 0; j < 16; j++) {
            float4 f = F4[j];
            #pragma unroll
            for (int k = 0; k < 16; k++) {
                float4 w = ws[k * 16 + j];
                acc[k] += f.x * w.x + f.y * w.y + f.z * w.z + f.w * w.w;
            }
        }
        #pragma unroll
        for (int r = 0; r < 8; r++) {
            float4 v;
            v.x = wc[r*4]*acc[0] + wc[r*4+1]*acc[1] + wc[r*4+2]*acc[2]  + wc[r*4+3]*acc[3];
            v.y = wc[r*4]*acc[4] + wc[r*4+1]*acc[5] + wc[r*4+2]*acc[6]  + wc[r*4+3]*acc[7];
            v.z = wc[r*4]*acc[8] + wc[r*4+1]*acc[9] + wc[r*4+2]*acc[10] + wc[r*4+3]*acc[11];
            v.w = 0.f;
            g_vtab[r * N_NODES + n] = v;     // lane-coalesced per r
        }
        float2 f = feats[n];
        contrib = (double)(f.x * acc[12] + f.y * acc[13] + acc[14] + acc[15]);
    }
    double bs = block_reduce(contrib, TPB_N);
    if (tid == 0) atomicAdd(&g_acc, bs);
}

// ---------------------------------------------------------------------------
// K2: edge pass + finalize. 128-thread blocks, 8 CTAs/SM (exact 64K-reg fit)
// -> 32 warps/SM for gather latency hiding; one wave (1184 blocks).
// 4 edges/iter via int4 indices; vtab indexed [rel][node].
// ---------------------------------------------------------------------------
__global__ void __launch_bounds__(TPB_E, 8)
k_edge(const float2* __restrict__ feats,
       const int* __restrict__ src, const int* __restrict__ dst,
       const int* __restrict__ et, const float* __restrict__ fc_b,
       int E, float* __restrict__ out)
{
    double contrib = 0.0;
    int nvec = E >> 2;
    const int4* s4p = (const int4*)src;
    const int4* d4p = (const int4*)dst;
    const int4* r4p = (const int4*)et;
    for (int i = blockIdx.x * TPB_E + threadIdx.x; i < nvec; i += GRID_E * TPB_E) {
        int4 s4 = s4p[i], d4 = d4p[i], r4 = r4p[i];
        float2 fa = feats[s4.x], fb = feats[s4.y], fc = feats[s4.z], fd = feats[s4.w];
        float4 va = g_vtab[r4.x * N_NODES + d4.x];
        float4 vb = g_vtab[r4.y * N_NODES + d4.y];
        float4 vc = g_vtab[r4.z * N_NODES + d4.z];
        float4 vd = g_vtab[r4.w * N_NODES + d4.w];
        float esum = fmaf(fa.x, va.x, fmaf(fa.y, va.y, va.z))
                   + fmaf(fb.x, vb.x, fmaf(fb.y, vb.y, vb.z))
                   + fmaf(fc.x, vc.x, fmaf(fc.y, vc.y, vc.z))
                   + fmaf(fd.x, vd.x, fmaf(fd.y, vd.y, vd.z));
        contrib += (double)esum;
    }
    for (int e = (nvec << 2) + blockIdx.x * TPB_E + threadIdx.x; e < E; e += GRID_E * TPB_E) {
        float2 f = feats[src[e]];
        float4 v = g_vtab[et[e] * N_NODES + dst[e]];
        contrib += (double)fmaf(f.x, v.x, fmaf(f.y, v.y, v.z));
    }

    double bs = block_reduce(contrib, TPB_E);
    if (threadIdx.x == 0) {
        atomicAdd(&g_acc, bs);
        __threadfence();
        unsigned d = atomicAdd(&g_done, 1u);
        if (d == GRID_E - 1) {
            double logit = atomicAdd(&g_acc, 0.0) + (double)fc_b[0];
            out[0] = (float)(1.0 / (1.0 + exp(-logit)));
            g_acc = 0.0;       // reset for next graph replay
            g_done = 0u;
            g_ready = 0u;
        }
    }
}

extern "C" void kernel_launch(void* const* d_in, const int* in_sizes, int n_in,
                              void* d_out, int out_size) {
    const float* features = (const float*)d_in[0];
    const int*   src      = (const int*)d_in[1];
    const int*   dst      = (const int*)d_in[2];
    const int*   etype    = (const int*)d_in[3];
    const float* W_in     = (const float*)d_in[4];
    const float* b_in     = (const float*)d_in[5];
    const float* w_comp   = (const float*)d_in[6];
    const float* bases    = (const float*)d_in[7];
    const float* loop_w   = (const float*)d_in[8];
    const float* h_bias   = (const float*)d_in[9];
    const float* fc_W     = (const float*)d_in[10];
    const float* fc_b     = (const float*)d_in[11];
    int E = in_sizes[1];

    k_node<<<(N_NODES + TPB_N - 1) / TPB_N, TPB_N>>>((const float2*)features,
                                                     W_in, b_in, w_comp, bases,
                                                     loop_w, h_bias, fc_W);
    k_edge<<<GRID_E, TPB_E>>>((const float2*)features, src, dst, etype,
                              fc_b, E, (float*)d_out);
}

// round 10
// speedup vs baseline: 1.2094x; 1.0088x over previous
#include <cuda_runtime.h>
#include <math.h>

#define N_NODES 50000
#define TPB_N   128
#define NPB     57           // nodes per block
#define GRID_N  888          // 148 SMs * 6 CTAs, NPB*GRID_N >= N_NODES
#define TPB_E   128
#define GRID_E  1184         // 148 SMs * 8 CTAs -> exactly one wave

// Scratch (allocation-free __device__ globals). Zero-initialized at load;
// K2's last block resets counters each launch -> deterministic across replays.
__device__ double   g_acc;
__device__ unsigned g_done;
__device__ unsigned g_ready;                // setup rows published (0..16)
__device__ float    g_Wt[16 * 64];          // 16 weight rows
__device__ float4   g_vtab[8 * N_NODES];    // [rel][node]: (v0, v1, vb, 0)

typedef unsigned long long u64;
#define FMA2(d, a, b) \
    asm("fma.rn.f32x2 %0, %1, %2, %0;" : "+l"(d) : "l"(a), "l"(b))

__device__ __forceinline__ double block_reduce(double v, int nthreads) {
    __shared__ double sh[8];
    int lane = threadIdx.x & 31, wid = threadIdx.x >> 5;
    #pragma unroll
    for (int off = 16; off; off >>= 1) v += __shfl_down_sync(0xffffffffu, v, off);
    if (lane == 0) sh[wid] = v;
    __syncthreads();
    int nw = nthreads >> 5;
    v = (threadIdx.x < nw) ? sh[threadIdx.x] : 0.0;
    if (wid == 0) {
        #pragma unroll
        for (int off = 4; off; off >>= 1) v += __shfl_down_sync(0xffffffffu, v, off);
    }
    return v;
}

// ---------------------------------------------------------------------------
// K1: node pass; blocks 0..15 also each compute ONE row of the 16x64 weight
// table (no redundancy), publish via g_ready. All 888 blocks are co-resident
// (6 CTAs/SM: smem ~17KB, regs <=64), so the spin cannot deadlock.
// Weight rows:
//   rows c*4+b (c<3,b<4): t[c][b][o] = sum_i hv[c][i]*bases[b,i,o]
//   rows 12..14:          sl[c][o]   = sum_i hv[c][i]*loop_w[i,o]
//   row  15:              h_bias
//   hv[0]=W_in[0,:], hv[1]=W_in[1,:], hv[2]=b_in
// Node math uses packed f32x2 FMAs (2x fp32 throughput); tile + ws are read
// from SMEM as ulonglong2 so no packing instructions are needed.
// vtab stored [rel][node] (coalesced warp stores).
// ---------------------------------------------------------------------------
#define TSTRIDE 68           // floats per padded tile row (16B-aligned rows)

__global__ void __launch_bounds__(TPB_N)
k_node(const float2* __restrict__ feats,
       const float* __restrict__ W_in, const float* __restrict__ b_in,
       const float* __restrict__ w_comp, const float* __restrict__ bases,
       const float* __restrict__ loop_w, const float* __restrict__ h_bias,
       const float* __restrict__ fcW)
{
    __shared__ float  tile[NPB * TSTRIDE];   // 15.5 KB
    __shared__ float4 ws[16 * 16];           // 16 rows x 64 floats
    __shared__ float  wc[32];
    __shared__ float  hv[64];
    __shared__ float  part[2][64];
    int tid = threadIdx.x;

    if (tid < 32) wc[tid] = w_comp[tid];

    // --- Setup duty for blocks 0..15: compute g_Wt row blockIdx.x ---
    if (blockIdx.x < 16) {
        int row = blockIdx.x;
        if (row == 15) {
            if (tid < 64) g_Wt[15 * 64 + tid] = h_bias[tid];
        } else {
            int c; const float* M;
            if (row < 12) { c = row >> 2; M = bases + (row & 3) * 4096; }
            else          { c = row - 12; M = loop_w; }
            if (tid < 64) hv[tid] = (c < 2) ? W_in[c * 64 + tid] : b_in[tid];
            __syncthreads();
            int o = tid & 63, q = tid >> 6;       // 2-way i-split of 32 each
            float s = 0.f;
            int i0 = q * 32;
            #pragma unroll 16
            for (int i = 0; i < 32; i++)
                s += hv[i0 + i] * __ldg(&M[(i0 + i) * 64 + o]);
            part[q][o] = s;
            __syncthreads();
            if (tid < 64)
                g_Wt[row * 64 + tid] = part[0][tid] + part[1][tid];
        }
        __syncthreads();
        if (tid == 0) {
            __threadfence();
            atomicAdd(&g_ready, 1u);
        }
    }

    // --- Stage this block's fcW tile into SMEM (coalesced warp loads) ---
    int nbase = blockIdx.x * NPB;
    int nblk  = min(NPB, N_NODES - nbase);   // may be <=0 for trailing blocks
    if (nblk > 0) {
        const float4* src4 = (const float4*)(fcW + (size_t)nbase * 64);
        int total4 = nblk * 16;
        for (int idx = tid; idx < total4; idx += TPB_N) {
            float4 f = src4[idx];
            int node = idx >> 4, j4 = idx & 15;
            ((float4*)(tile + node * TSTRIDE))[j4] = f;
        }
    }

    // --- Wait for all 16 weight rows, then pull them into SMEM ---
    if (tid == 0) {
        while (atomicAdd(&g_ready, 0u) < 16u) { }
        __threadfence();
    }
    __syncthreads();
    for (int i = tid; i < 16 * 16; i += TPB_N)
        ws[i] = ((const float4*)g_Wt)[i];
    __syncthreads();

    // --- Per-node math (packed f32x2) ---
    double contrib = 0.0;
    if (nblk > 0 && tid < nblk) {
        int n = nbase + tid;
        const ulonglong2* F2 = (const ulonglong2*)(tile + tid * TSTRIDE);
        const ulonglong2* W2 = (const ulonglong2*)ws;
        u64 acc2[16];
        #pragma unroll
        for (int k = 0; k < 16; k++) acc2[k] = 0ull;
        #pragma unroll 4
        for (int j = 0; j < 16; j++) {
            ulonglong2 f = F2[j];
            #pragma unroll
            for (int k = 0; k < 16; k++) {
                ulonglong2 w = W2[k * 16 + j];
                FMA2(acc2[k], f.x, w.x);
                FMA2(acc2[k], f.y, w.y);
            }
        }
        float acc[16];
        #pragma unroll
        for (int k = 0; k < 16; k++) {
            union { u64 u; float2 f2; } cv; cv.u = acc2[k];
            acc[k] = cv.f2.x + cv.f2.y;
        }
        #pragma unroll
        for (int r = 0; r < 8; r++) {
            float4 v;
            v.x = wc[r*4]*acc[0] + wc[r*4+1]*acc[1] + wc[r*4+2]*acc[2]  + wc[r*4+3]*acc[3];
            v.y = wc[r*4]*acc[4] + wc[r*4+1]*acc[5] + wc[r*4+2]*acc[6]  + wc[r*4+3]*acc[7];
            v.z = wc[r*4]*acc[8] + wc[r*4+1]*acc[9] + wc[r*4+2]*acc[10] + wc[r*4+3]*acc[11];
            v.w = 0.f;
            g_vtab[r * N_NODES + n] = v;     // lane-coalesced per r
        }
        float2 f = feats[n];
        contrib = (double)(f.x * acc[12] + f.y * acc[13] + acc[14] + acc[15]);
    }
    double bs = block_reduce(contrib, TPB_N);
    if (tid == 0) atomicAdd(&g_acc, bs);
}

// ---------------------------------------------------------------------------
// K2: edge pass + finalize (unchanged from R9). One wave (1184 blocks),
// 4 edges/iter via int4 indices; vtab indexed [rel][node].
// ---------------------------------------------------------------------------
__global__ void __launch_bounds__(TPB_E, 8)
k_edge(const float2* __restrict__ feats,
       const int* __restrict__ src, const int* __restrict__ dst,
       const int* __restrict__ et, const float* __restrict__ fc_b,
       int E, float* __restrict__ out)
{
    double contrib = 0.0;
    int nvec = E >> 2;
    const int4* s4p = (const int4*)src;
    const int4* d4p = (const int4*)dst;
    const int4* r4p = (const int4*)et;
    for (int i = blockIdx.x * TPB_E + threadIdx.x; i < nvec; i += GRID_E * TPB_E) {
        int4 s4 = s4p[i], d4 = d4p[i], r4 = r4p[i];
        float2 fa = feats[s4.x], fb = feats[s4.y], fc = feats[s4.z], fd = feats[s4.w];
        float4 va = g_vtab[r4.x * N_NODES + d4.x];
        float4 vb = g_vtab[r4.y * N_NODES + d4.y];
        float4 vc = g_vtab[r4.z * N_NODES + d4.z];
        float4 vd = g_vtab[r4.w * N_NODES + d4.w];
        float esum = fmaf(fa.x, va.x, fmaf(fa.y, va.y, va.z))
                   + fmaf(fb.x, vb.x, fmaf(fb.y, vb.y, vb.z))
                   + fmaf(fc.x, vc.x, fmaf(fc.y, vc.y, vc.z))
                   + fmaf(fd.x, vd.x, fmaf(fd.y, vd.y, vd.z));
        contrib += (double)esum;
    }
    for (int e = (nvec << 2) + blockIdx.x * TPB_E + threadIdx.x; e < E; e += GRID_E * TPB_E) {
        float2 f = feats[src[e]];
        float4 v = g_vtab[et[e] * N_NODES + dst[e]];
        contrib += (double)fmaf(f.x, v.x, fmaf(f.y, v.y, v.z));
    }

    double bs = block_reduce(contrib, TPB_E);
    if (threadIdx.x == 0) {
        atomicAdd(&g_acc, bs);
        __threadfence();
        unsigned d = atomicAdd(&g_done, 1u);
        if (d == GRID_E - 1) {
            double logit = atomicAdd(&g_acc, 0.0) + (double)fc_b[0];
            out[0] = (float)(1.0 / (1.0 + exp(-logit)));
            g_acc = 0.0;       // reset for next graph replay
            g_done = 0u;
            g_ready = 0u;
        }
    }
}

extern "C" void kernel_launch(void* const* d_in, const int* in_sizes, int n_in,
                              void* d_out, int out_size) {
    const float* features = (const float*)d_in[0];
    const int*   src      = (const int*)d_in[1];
    const int*   dst      = (const int*)d_in[2];
    const int*   etype    = (const int*)d_in[3];
    const float* W_in     = (const float*)d_in[4];
    const float* b_in     = (const float*)d_in[5];
    const float* w_comp   = (const float*)d_in[6];
    const float* bases    = (const float*)d_in[7];
    const float* loop_w   = (const float*)d_in[8];
    const float* h_bias   = (const float*)d_in[9];
    const float* fc_W     = (const float*)d_in[10];
    const float* fc_b     = (const float*)d_in[11];
    int E = in_sizes[1];

    k_node<<<GRID_N, TPB_N>>>((const float2*)features,
                              W_in, b_in, w_comp, bases,
                              loop_w, h_bias, fc_W);
    k_edge<<<GRID_E, TPB_E>>>((const float2*)features, src, dst, etype,
                              fc_b, E, (float*)d_out);
}

// round 11
// speedup vs baseline: 1.3007x; 1.0755x over previous
#include <cuda_runtime.h>
#include <math.h>

#define N_NODES 50000
#define TPB_N   128
#define NPB     114          // nodes per block
#define GRID_N  444          // 148 * 3, NPB*GRID_N = 50616 >= N_NODES
#define TPB_E   128
#define GRID_E  888          // 148 SMs * 6 CTAs -> exactly one wave

// Scratch (allocation-free __device__ globals). Zero-initialized at load;
// K2's last block resets counters each launch -> deterministic across replays.
__device__ double   g_acc;
__device__ unsigned g_done;
__device__ unsigned g_ready;                // setup rows published (0..16)
__device__ float    g_Wt[16 * 64];          // 16 weight rows
__device__ float4   g_vtab[8 * N_NODES];    // [rel][node]: (v0, v1, vb, 0)

typedef unsigned long long u64;
#define FMA2(d, a, b) \
    asm("fma.rn.f32x2 %0, %1, %2, %0;" : "+l"(d) : "l"(a), "l"(b))

__device__ __forceinline__ double block_reduce(double v, int nthreads) {
    __shared__ double sh[8];
    int lane = threadIdx.x & 31, wid = threadIdx.x >> 5;
    #pragma unroll
    for (int off = 16; off; off >>= 1) v += __shfl_down_sync(0xffffffffu, v, off);
    if (lane == 0) sh[wid] = v;
    __syncthreads();
    int nw = nthreads >> 5;
    v = (threadIdx.x < nw) ? sh[threadIdx.x] : 0.0;
    if (wid == 0) {
        #pragma unroll
        for (int off = 4; off; off >>= 1) v += __shfl_down_sync(0xffffffffu, v, off);
    }
    return v;
}

// ---------------------------------------------------------------------------
// K1: node pass; blocks 0..15 also each compute ONE row of the 16x64 weight
// table (no redundancy), publish via g_ready. All 444 blocks are co-resident
// (3 CTAs/SM at ~32KB smem), so the spin cannot deadlock.
// Weight rows:
//   rows c*4+b (c<3,b<4): t[c][b][o] = sum_i hv[c][i]*bases[b,i,o]
//   rows 12..14:          sl[c][o]   = sum_i hv[c][i]*loop_w[i,o]
//   row  15:              h_bias
//   hv[0]=W_in[0,:], hv[1]=W_in[1,:], hv[2]=b_in
// Node math uses packed f32x2 FMAs; tile + ws read from SMEM as ulonglong2.
// vtab stored [rel][node] (coalesced warp stores).
// ---------------------------------------------------------------------------
#define TSTRIDE 68           // floats per padded tile row (16B-aligned rows)

__global__ void __launch_bounds__(TPB_N)
k_node(const float2* __restrict__ feats,
       const float* __restrict__ W_in, const float* __restrict__ b_in,
       const float* __restrict__ w_comp, const float* __restrict__ bases,
       const float* __restrict__ loop_w, const float* __restrict__ h_bias,
       const float* __restrict__ fcW)
{
    __shared__ float  tile[NPB * TSTRIDE];   // 31 KB
    __shared__ float4 ws[16 * 16];           // 16 rows x 64 floats
    __shared__ float  wc[32];
    __shared__ float  hv[64];
    __shared__ float  part[2][64];
    int tid = threadIdx.x;

    if (tid < 32) wc[tid] = w_comp[tid];

    // --- Setup duty for blocks 0..15: compute g_Wt row blockIdx.x ---
    if (blockIdx.x < 16) {
        int row = blockIdx.x;
        if (row == 15) {
            if (tid < 64) g_Wt[15 * 64 + tid] = h_bias[tid];
        } else {
            int c; const float* M;
            if (row < 12) { c = row >> 2; M = bases + (row & 3) * 4096; }
            else          { c = row - 12; M = loop_w; }
            if (tid < 64) hv[tid] = (c < 2) ? W_in[c * 64 + tid] : b_in[tid];
            __syncthreads();
            int o = tid & 63, q = tid >> 6;       // 2-way i-split of 32 each
            float s = 0.f;
            int i0 = q * 32;
            #pragma unroll 16
            for (int i = 0; i < 32; i++)
                s += hv[i0 + i] * __ldg(&M[(i0 + i) * 64 + o]);
            part[q][o] = s;
            __syncthreads();
            if (tid < 64)
                g_Wt[row * 64 + tid] = part[0][tid] + part[1][tid];
        }
        __syncthreads();
        if (tid == 0) {
            __threadfence();
            atomicAdd(&g_ready, 1u);
        }
    }

    // --- Stage this block's fcW tile into SMEM (coalesced warp loads) ---
    int nbase = blockIdx.x * NPB;
    int nblk  = min(NPB, N_NODES - nbase);
    if (nblk > 0) {
        const float4* src4 = (const float4*)(fcW + (size_t)nbase * 64);
        int total4 = nblk * 16;
        for (int idx = tid; idx < total4; idx += TPB_N) {
            float4 f = src4[idx];
            int node = idx >> 4, j4 = idx & 15;
            ((float4*)(tile + node * TSTRIDE))[j4] = f;
        }
    }

    // --- Wait for all 16 weight rows, then pull them into SMEM ---
    if (tid == 0) {
        while (atomicAdd(&g_ready, 0u) < 16u) { }
        __threadfence();
    }
    __syncthreads();
    for (int i = tid; i < 16 * 16; i += TPB_N)
        ws[i] = ((const float4*)g_Wt)[i];
    __syncthreads();

    // --- Per-node math (packed f32x2) ---
    double contrib = 0.0;
    if (nblk > 0 && tid < nblk) {
        int n = nbase + tid;
        const ulonglong2* F2 = (const ulonglong2*)(tile + tid * TSTRIDE);
        const ulonglong2* W2 = (const ulonglong2*)ws;
        u64 acc2[16];
        #pragma unroll
        for (int k = 0; k < 16; k++) acc2[k] = 0ull;
        #pragma unroll 4
        for (int j = 0; j < 16; j++) {
            ulonglong2 f = F2[j];
            #pragma unroll
            for (int k = 0; k < 16; k++) {
                ulonglong2 w = W2[k * 16 + j];
                FMA2(acc2[k], f.x, w.x);
                FMA2(acc2[k], f.y, w.y);
            }
        }
        float acc[16];
        #pragma unroll
        for (int k = 0; k < 16; k++) {
            union { u64 u; float2 f2; } cv; cv.u = acc2[k];
            acc[k] = cv.f2.x + cv.f2.y;
        }
        #pragma unroll
        for (int r = 0; r < 8; r++) {
            float4 v;
            v.x = wc[r*4]*acc[0] + wc[r*4+1]*acc[1] + wc[r*4+2]*acc[2]  + wc[r*4+3]*acc[3];
            v.y = wc[r*4]*acc[4] + wc[r*4+1]*acc[5] + wc[r*4+2]*acc[6]  + wc[r*4+3]*acc[7];
            v.z = wc[r*4]*acc[8] + wc[r*4+1]*acc[9] + wc[r*4+2]*acc[10] + wc[r*4+3]*acc[11];
            v.w = 0.f;
            g_vtab[r * N_NODES + n] = v;     // lane-coalesced per r
        }
        float2 f = feats[n];
        contrib = (double)(f.x * acc[12] + f.y * acc[13] + acc[14] + acc[15]);
    }
    double bs = block_reduce(contrib, TPB_N);
    if (tid == 0) atomicAdd(&g_acc, bs);
}

// ---------------------------------------------------------------------------
// K2: edge pass + finalize. Software-pipelined: next iteration's index loads
// issue BEFORE the current iteration's gathers are consumed, hiding the
// index-load latency under the gather round. One wave (888 blocks @6/SM).
// ---------------------------------------------------------------------------
__global__ void __launch_bounds__(TPB_E, 6)
k_edge(const float2* __restrict__ feats,
       const int* __restrict__ src, const int* __restrict__ dst,
       const int* __restrict__ et, const float* __restrict__ fc_b,
       int E, float* __restrict__ out)
{
    double contrib = 0.0;
    int nvec = E >> 2;
    const int4* s4p = (const int4*)src;
    const int4* d4p = (const int4*)dst;
    const int4* r4p = (const int4*)et;
    const int stride = GRID_E * TPB_E;

    int i = blockIdx.x * TPB_E + threadIdx.x;
    if (i < nvec) {
        int4 s4 = s4p[i], d4 = d4p[i], r4 = r4p[i];
        while (true) {
            int inext = i + stride;
            bool more = inext < nvec;
            int4 s4n, d4n, r4n;
            if (more) {                      // prefetch next indices early
                s4n = s4p[inext]; d4n = d4p[inext]; r4n = r4p[inext];
            }
            // gathers + math for current group
            float2 fa = feats[s4.x], fb = feats[s4.y];
            float2 fc = feats[s4.z], fd = feats[s4.w];
            float4 va = g_vtab[r4.x * N_NODES + d4.x];
            float4 vb = g_vtab[r4.y * N_NODES + d4.y];
            float4 vc = g_vtab[r4.z * N_NODES + d4.z];
            float4 vd = g_vtab[r4.w * N_NODES + d4.w];
            float esum = fmaf(fa.x, va.x, fmaf(fa.y, va.y, va.z))
                       + fmaf(fb.x, vb.x, fmaf(fb.y, vb.y, vb.z))
                       + fmaf(fc.x, vc.x, fmaf(fc.y, vc.y, vc.z))
                       + fmaf(fd.x, vd.x, fmaf(fd.y, vd.y, vd.z));
            contrib += (double)esum;
            if (!more) break;
            s4 = s4n; d4 = d4n; r4 = r4n; i = inext;
        }
    }
    // tail edges (if E not multiple of 4)
    for (int e = (nvec << 2) + blockIdx.x * TPB_E + threadIdx.x; e < E; e += stride) {
        float2 f = feats[src[e]];
        float4 v = g_vtab[et[e] * N_NODES + dst[e]];
        contrib += (double)fmaf(f.x, v.x, fmaf(f.y, v.y, v.z));
    }

    double bs = block_reduce(contrib, TPB_E);
    if (threadIdx.x == 0) {
        atomicAdd(&g_acc, bs);
        __threadfence();
        unsigned d = atomicAdd(&g_done, 1u);
        if (d == GRID_E - 1) {
            double logit = atomicAdd(&g_acc, 0.0) + (double)fc_b[0];
            out[0] = (float)(1.0 / (1.0 + exp(-logit)));
            g_acc = 0.0;       // reset for next graph replay
            g_done = 0u;
            g_ready = 0u;
        }
    }
}

extern "C" void kernel_launch(void* const* d_in, const int* in_sizes, int n_in,
                              void* d_out, int out_size) {
    const float* features = (const float*)d_in[0];
    const int*   src      = (const int*)d_in[1];
    const int*   dst      = (const int*)d_in[2];
    const int*   etype    = (const int*)d_in[3];
    const float* W_in     = (const float*)d_in[4];
    const float* b_in     = (const float*)d_in[5];
    const float* w_comp   = (const float*)d_in[6];
    const float* bases    = (const float*)d_in[7];
    const float* loop_w   = (const float*)d_in[8];
    const float* h_bias   = (const float*)d_in[9];
    const float* fc_W     = (const float*)d_in[10];
    const float* fc_b     = (const float*)d_in[11];
    int E = in_sizes[1];

    k_node<<<GRID_N, TPB_N>>>((const float2*)features,
                              W_in, b_in, w_comp, bases,
                              loop_w, h_bias, fc_W);
    k_edge<<<GRID_E, TPB_E>>>((const float2*)features, src, dst, etype,
                              fc_b, E, (float*)d_out);
}